// round 3
// baseline (speedup 1.0000x reference)
#include <cuda_runtime.h>
#include <math.h>

// ---------------------------------------------------------------------------
// QuantPINN: 7x quant_linear MLP with per-tensor int8 fake quantization.
// Exact-integer strategy: xq @ wq.T = (sx*sw) * (Xint @ Wint^T), int8 dp4a GEMM.
// Quantization: IEEE-division semantics (fast mul path + exact-div fallback
// near round boundaries). tanh: bit-exact XLA rational approximation with
// clamp +-7.90531110763549805.
// ---------------------------------------------------------------------------

#define N_MAX 262144
#define HID   100
#define KG    25          // 100 / 4 int8s per packed word
#define QMAXF 127.0f

// Ping-pong activation buffers (fp32, exact path)
__device__ float g_hA[N_MAX * HID];
__device__ float g_hB[N_MAX * HID];
// Packed int8 weights for hidden layers 2..6: [layer][kgroup][out-col padded to 104]
__device__ int   g_Wp[5][KG][104];
// Layer 1 integer weights [100][2]
__device__ int   g_W1i[HID * 2];
// Output layer packed weights [2][25]
__device__ int   g_Wpo[2][KG];
// Per-layer weight scales: 0=W1, 1..5=W2..W6, 6=Wout
__device__ float g_sw[7];
// Activation |max| slots as float bits: 0=input x, 1..6 = h1..h6
__device__ int   g_slots[8];

// ---------------------------------------------------------------------------
// XLA ElementalIrEmitter::EmitTanh, bit-exact:
//   if |x| < 0.0004: x
//   else: xc = clamp(x, -7.90531110763549805, 7.90531110763549805)
//         xc * P(xc^2) / Q(xc^2), non-fused mul/add Horner, IEEE divide.
__device__ __forceinline__ float xla_tanh(float x) {
    const float kMax = 7.90531110763549805f;
    float xc = fmaxf(-kMax, fminf(x, kMax));
    float x2 = __fmul_rn(xc, xc);
    float p = -2.76076847742355e-16f;
    p = __fadd_rn(__fmul_rn(p, x2), 2.00018790482477e-13f);
    p = __fadd_rn(__fmul_rn(p, x2), -8.60467152213735e-11f);
    p = __fadd_rn(__fmul_rn(p, x2), 5.12229709037114e-08f);
    p = __fadd_rn(__fmul_rn(p, x2), 1.48572235717979e-05f);
    p = __fadd_rn(__fmul_rn(p, x2), 6.37261928875436e-04f);
    p = __fadd_rn(__fmul_rn(p, x2), 4.89352455891786e-03f);
    float num = __fmul_rn(xc, p);
    float q = 1.19825839466702e-06f;
    q = __fadd_rn(__fmul_rn(q, x2), 1.18534705686654e-04f);
    q = __fadd_rn(__fmul_rn(q, x2), 2.26843463243900e-03f);
    q = __fadd_rn(__fmul_rn(q, x2), 4.89352518554385e-03f);
    float r = __fdiv_rn(num, q);
    return (fabsf(x) < 0.0004f) ? x : r;
}

__device__ __forceinline__ float read_scale(int slot) {
    float m = __int_as_float(g_slots[slot]);
    float s = __fdiv_rn(m, QMAXF);
    return fmaxf(s, 1e-12f);
}

// Exact: clip(round(v / s), -127, 127) with IEEE division + half-even round.
__device__ __forceinline__ int q8(float v, float s) {
    float x = __fdiv_rn(v, s);
    x = fminf(fmaxf(x, -127.0f), 127.0f);
    return __float2int_rn(x);
}

// Fast path: multiply by precomputed fl(1/s); exact-divide only when within
// 2 ulp of a .5 rounding boundary (result identical to q8).
__device__ __forceinline__ int q8f(float v, float s, float inv) {
    float r = __fmul_rn(v, inv);
    float rr = rintf(r);
    float d = fabsf(__fadd_rn(r, -rr));          // in [0, 0.5]
    if (fabsf(d - 0.5f) < (4e-7f * fabsf(r) + 1e-9f))
        r = __fdiv_rn(v, s);
    r = fminf(fmaxf(r, -127.0f), 127.0f);
    return __float2int_rn(r);
}

__device__ __forceinline__ int pack4(int a, int b, int c, int d) {
    return (a & 0xFF) | ((b & 0xFF) << 8) | ((c & 0xFF) << 16) | ((d & 0xFF) << 24);
}

__device__ __forceinline__ float bias_q(float b, float sb) {
    float r = rintf(__fdiv_rn(b, sb));
    r = fminf(fmaxf(r, -128.0f), 127.0f);
    return __fmul_rn(r, sb);
}

__device__ __forceinline__ void warp_max_atomic(float v, int slot) {
    #pragma unroll
    for (int off = 16; off > 0; off >>= 1)
        v = fmaxf(v, __shfl_xor_sync(0xffffffffu, v, off));
    if ((threadIdx.x & 31) == 0)
        atomicMax(&g_slots[slot], __float_as_int(v));  // v >= 0 -> bits monotone
}

// ---------------------------------------------------------------------------
// 0) zero the scale slots
__global__ void k_zero_slots() {
    if (threadIdx.x < 8) g_slots[threadIdx.x] = 0;
}

// 1) global max of |concat(z,t)|  -> slot 0
__global__ void k_input_max(const float* __restrict__ z, const float* __restrict__ t, int n) {
    float m = 0.0f;
    for (int i = blockIdx.x * blockDim.x + threadIdx.x; i < n; i += gridDim.x * blockDim.x)
        m = fmaxf(m, fmaxf(fabsf(z[i]), fabsf(t[i])));
    warp_max_atomic(m, 0);
}

// 2) per-layer weight quantization + packing. blockIdx.x = layer 0..6
__global__ void k_weight_prep(const float* __restrict__ W1,
                              const float* __restrict__ W2, const float* __restrict__ W3,
                              const float* __restrict__ W4, const float* __restrict__ W5,
                              const float* __restrict__ W6, const float* __restrict__ Wout) {
    int l = blockIdx.x;
    const float* W;
    int cnt;
    if (l == 0)      { W = W1;   cnt = HID * 2; }
    else if (l == 6) { W = Wout; cnt = 2 * HID; }
    else {
        const float* Ws_[5] = {W2, W3, W4, W5, W6};
        W = Ws_[l - 1]; cnt = HID * HID;
    }

    __shared__ float red[256];
    float m = 0.0f;
    for (int i = threadIdx.x; i < cnt; i += 256) m = fmaxf(m, fabsf(W[i]));
    red[threadIdx.x] = m;
    __syncthreads();
    for (int s = 128; s > 0; s >>= 1) {
        if (threadIdx.x < s) red[threadIdx.x] = fmaxf(red[threadIdx.x], red[threadIdx.x + s]);
        __syncthreads();
    }
    __shared__ float s_sw;
    if (threadIdx.x == 0) {
        float sw = fmaxf(__fdiv_rn(red[0], QMAXF), 1e-12f);
        g_sw[l] = sw;
        s_sw = sw;
    }
    __syncthreads();
    float sw = s_sw;

    if (l == 0) {
        for (int i = threadIdx.x; i < HID * 2; i += 256)
            g_W1i[i] = q8(W[i], sw);
    } else if (l == 6) {
        for (int w = threadIdx.x; w < 2 * KG; w += 256) {
            int o = w / KG, kg = w % KG;
            int base = o * HID + kg * 4;
            g_Wpo[o][kg] = pack4(q8(W[base + 0], sw), q8(W[base + 1], sw),
                                 q8(W[base + 2], sw), q8(W[base + 3], sw));
        }
    } else {
        for (int w = threadIdx.x; w < KG * 104; w += 256) {
            int kg = w / 104, c = w % 104;
            int p = 0;
            if (c < HID) {
                int base = c * HID + kg * 4;   // W row-major [out][in]
                p = pack4(q8(W[base + 0], sw), q8(W[base + 1], sw),
                          q8(W[base + 2], sw), q8(W[base + 3], sw));
            }
            g_Wp[l - 1][kg][c] = p;
        }
    }
}

// ---------------------------------------------------------------------------
// 3) layer 1: x=[z,t] (K=2) -> h1 [N,100], tanh, max -> slot 1
//    thread handles 4 consecutive outputs of one row -> coalesced float4 store.
//    Weights + quantized bias staged in shared memory.
__global__ void k_layer1(const float* __restrict__ z, const float* __restrict__ t,
                         const float* __restrict__ b1, int n) {
    __shared__ int   Wls[HID * 2];
    __shared__ float bls[HID];
    __shared__ float s_consts[3];   // sx, sb, inv_sx

    int tid = threadIdx.x;
    if (tid == 0) {
        float sx = read_scale(0);
        float sb = __fmul_rn(sx, g_sw[0]);
        s_consts[0] = sx;
        s_consts[1] = sb;
        s_consts[2] = __fdiv_rn(1.0f, sx);
    }
    if (tid < HID * 2) Wls[tid] = g_W1i[tid];
    __syncthreads();
    float sx  = s_consts[0];
    float sb  = s_consts[1];
    float inv = s_consts[2];
    if (tid < HID) bls[tid] = bias_q(b1[tid], sb);
    __syncthreads();

    int idx = blockIdx.x * blockDim.x + tid;
    int i  = idx / 25;
    int og = idx % 25;
    float vmax = 0.0f;
    if (i < n) {
        int zi = q8f(z[i], sx, inv);
        int ti = q8f(t[i], sx, inv);
        float4 hv;
        float* hp = &hv.x;
        #pragma unroll
        for (int j = 0; j < 4; j++) {
            int o = og * 4 + j;
            int acc = zi * Wls[o * 2] + ti * Wls[o * 2 + 1];
            float y = (float)acc * sb + bls[o];
            float h = xla_tanh(y);
            hp[j] = h;
            vmax = fmaxf(vmax, fabsf(h));
        }
        ((float4*)(g_hA + (size_t)i * HID))[og] = hv;
    }
    warp_max_atomic(vmax, 1);
}

// ---------------------------------------------------------------------------
// 4) hidden layer: quantize-in, int8 dp4a GEMM 128x100 (K=100), tanh, max.
//    416 threads = 13 warps; thread tile = 4 rows x 8 cols (out padded to 104).
__global__ void __launch_bounds__(416, 2)
k_hidden(const float* __restrict__ bias, int lidx, int dir, int n) {
    const float* hin  = dir ? g_hB : g_hA;
    float*       hout = dir ? g_hA : g_hB;

    __shared__ __align__(16) int Xs[KG][128];
    __shared__ __align__(16) int Ws[KG][104];
    __shared__ float bqs[104];

    int tid = threadIdx.x;
    size_t row0 = (size_t)blockIdx.x * 128;

    float sx = read_scale(lidx);          // slot_in == lidx (1..5)
    float sw = g_sw[lidx];
    float sb = __fmul_rn(sx, sw);
    float inv = __fdiv_rn(1.0f, sx);

    // quantize input tile: 128 rows x 25 packed words
    const float4* src = (const float4*)(hin + row0 * HID);
    for (int w = tid; w < 128 * KG; w += 416) {
        int r = w / KG, kg = w % KG;
        int p = 0;
        if (row0 + (size_t)r < (size_t)n) {
            float4 v = src[r * KG + kg];
            p = pack4(q8f(v.x, sx, inv), q8f(v.y, sx, inv),
                      q8f(v.z, sx, inv), q8f(v.w, sx, inv));
        }
        Xs[kg][r] = p;
    }
    // copy packed weights
    const int* wp = &g_Wp[lidx - 1][0][0];
    for (int w = tid; w < KG * 104; w += 416)
        ((int*)Ws)[w] = wp[w];
    // quantized bias
    if (tid < 104) {
        float bq = 0.0f;
        if (tid < HID) bq = bias_q(bias[tid], sb);
        bqs[tid] = bq;
    }
    __syncthreads();

    int cg = tid % 13, rg = tid / 13;
    int c0 = cg * 8, r0 = rg * 4;

    int acc[4][8];
    #pragma unroll
    for (int r = 0; r < 4; r++)
        #pragma unroll
        for (int c = 0; c < 8; c++) acc[r][c] = 0;

    for (int kg = 0; kg < KG; kg++) {
        int4 xv = *(const int4*)&Xs[kg][r0];
        int4 w0 = *(const int4*)&Ws[kg][c0];
        int4 w1 = *(const int4*)&Ws[kg][c0 + 4];
        int xr[4] = {xv.x, xv.y, xv.z, xv.w};
        int wr[8] = {w0.x, w0.y, w0.z, w0.w, w1.x, w1.y, w1.z, w1.w};
        #pragma unroll
        for (int r = 0; r < 4; r++)
            #pragma unroll
            for (int c = 0; c < 8; c++)
                acc[r][c] = __dp4a(xr[r], wr[c], acc[r][c]);
    }

    int nvalid = (c0 + 8 <= HID) ? 8 : 4;   // cg==12 -> cols 96..99 valid
    float vmax = 0.0f;
    #pragma unroll
    for (int r = 0; r < 4; r++) {
        size_t row = row0 + (size_t)(r0 + r);
        float o[8];
        #pragma unroll
        for (int c = 0; c < 8; c++) {
            float y = (float)acc[r][c] * sb + bqs[c0 + c];
            o[c] = xla_tanh(y);
        }
        if (row < (size_t)n) {
            #pragma unroll
            for (int c = 0; c < 8; c++)
                if (c < nvalid) vmax = fmaxf(vmax, fabsf(o[c]));
            float* dst = hout + row * HID + c0;
            float4 v0 = make_float4(o[0], o[1], o[2], o[3]);
            *(float4*)dst = v0;
            if (nvalid == 8) {
                float4 v1 = make_float4(o[4], o[5], o[6], o[7]);
                *(float4*)(dst + 4) = v1;
            }
        }
    }
    warp_max_atomic(vmax, lidx + 1);
}

// ---------------------------------------------------------------------------
// 5) output layer: [N,100] -> [N,2], no tanh. 64 rows per block.
__global__ void k_out(const float* __restrict__ bout, float* __restrict__ out,
                      int dir, int n) {
    const float* hin = dir ? g_hB : g_hA;
    __shared__ int Xs[KG][64];
    __shared__ float s_bq[2];

    int tid = threadIdx.x;
    size_t row0 = (size_t)blockIdx.x * 64;

    float sx = read_scale(6);
    float sw = g_sw[6];
    float sb = __fmul_rn(sx, sw);
    float inv = __fdiv_rn(1.0f, sx);

    const float4* src = (const float4*)(hin + row0 * HID);
    for (int w = tid; w < 64 * KG; w += 256) {
        int r = w / KG, kg = w % KG;
        int p = 0;
        if (row0 + (size_t)r < (size_t)n) {
            float4 v = src[r * KG + kg];
            p = pack4(q8f(v.x, sx, inv), q8f(v.y, sx, inv),
                      q8f(v.z, sx, inv), q8f(v.w, sx, inv));
        }
        Xs[kg][r] = p;
    }
    if (tid < 2) s_bq[tid] = bias_q(bout[tid], sb);
    __syncthreads();

    if (tid < 128) {
        int r = tid >> 1, o = tid & 1;
        size_t row = row0 + (size_t)r;
        if (row < (size_t)n) {
            int wv[KG];
            #pragma unroll
            for (int kg = 0; kg < KG; kg++) wv[kg] = g_Wpo[o][kg];
            int acc = 0;
            #pragma unroll
            for (int kg = 0; kg < KG; kg++)
                acc = __dp4a(Xs[kg][r], wv[kg], acc);
            out[row * 2 + o] = (float)acc * sb + s_bq[o];
        }
    }
}

// ---------------------------------------------------------------------------

extern "C" void kernel_launch(void* const* d_in, const int* in_sizes, int n_in,
                              void* d_out, int out_size) {
    const float* z    = (const float*)d_in[0];
    const float* t    = (const float*)d_in[1];
    const float* W1   = (const float*)d_in[2];
    const float* b1   = (const float*)d_in[3];
    const float* W2   = (const float*)d_in[4];
    const float* b2   = (const float*)d_in[5];
    const float* W3   = (const float*)d_in[6];
    const float* b3   = (const float*)d_in[7];
    const float* W4   = (const float*)d_in[8];
    const float* b4   = (const float*)d_in[9];
    const float* W5   = (const float*)d_in[10];
    const float* b5   = (const float*)d_in[11];
    const float* W6   = (const float*)d_in[12];
    const float* b6   = (const float*)d_in[13];
    const float* Wout = (const float*)d_in[14];
    const float* bout = (const float*)d_in[15];
    int n = in_sizes[0];

    k_zero_slots<<<1, 32>>>();
    k_input_max<<<512, 256>>>(z, t, n);
    k_weight_prep<<<7, 256>>>(W1, W2, W3, W4, W5, W6, Wout);

    int l1_blocks = (n * 25 + 255) / 256;
    k_layer1<<<l1_blocks, 256>>>(z, t, b1, n);

    int hblocks = (n + 127) / 128;
    k_hidden<<<hblocks, 416>>>(b2, 1, 0, n);   // A -> B
    k_hidden<<<hblocks, 416>>>(b3, 2, 1, n);   // B -> A
    k_hidden<<<hblocks, 416>>>(b4, 3, 0, n);   // A -> B
    k_hidden<<<hblocks, 416>>>(b5, 4, 1, n);   // B -> A
    k_hidden<<<hblocks, 416>>>(b6, 5, 0, n);   // A -> B

    int oblocks = (n + 63) / 64;
    k_out<<<oblocks, 256>>>(bout, (float*)d_out, 1, n);   // read B
}

// round 4
// speedup vs baseline: 4.8271x; 4.8271x over previous
#include <cuda_runtime.h>
#include <math.h>

// ---------------------------------------------------------------------------
// QuantPINN: after input quantization the whole network depends only on the
// int8 pair (zi, ti) -> at most 255*255 = 65025 distinct rows. Dedup: run the
// 7-layer quantized MLP on the present codes only, then gather per row.
// Exact-integer GEMM via dp4a; IEEE-division quantization; XLA rational tanh.
// ---------------------------------------------------------------------------

#define N_MAX  262144
#define HID    100
#define KG     25          // 100 / 4 int8s per packed word
#define QMAXF  127.0f
#define NCODE  65025       // 255 * 255
#define MAXROW 65152       // NCODE padded up

// Activation ping-pong for distinct rows (L2-resident: 26MB each)
__device__ float g_hA[MAXROW * HID];
__device__ float g_hB[MAXROW * HID];
// Packed int8 weights hidden layers 2..6: [layer][kgroup][out padded to 104]
__device__ int   g_Wp[5][KG][104];
__device__ int   g_W1i[HID * 2];     // layer1 integer weights [100][2]
__device__ int   g_Wpo[2][KG];       // output layer packed weights
__device__ float g_sw[7];            // weight scales
__device__ int   g_slots[8];         // activation |max| as float bits
// Dedup machinery
__device__ int            g_code[N_MAX];
__device__ unsigned char  g_present[NCODE];
__device__ int            g_list[NCODE];
__device__ int            g_inv[NCODE];
__device__ int            g_cnt;
__device__ float          g_table2[NCODE * 2];

// ---------------------------------------------------------------------------
__device__ __forceinline__ float xla_tanh(float x) {
    const float kMax = 7.90531110763549805f;
    float xc = fmaxf(-kMax, fminf(x, kMax));
    float x2 = __fmul_rn(xc, xc);
    float p = -2.76076847742355e-16f;
    p = __fadd_rn(__fmul_rn(p, x2), 2.00018790482477e-13f);
    p = __fadd_rn(__fmul_rn(p, x2), -8.60467152213735e-11f);
    p = __fadd_rn(__fmul_rn(p, x2), 5.12229709037114e-08f);
    p = __fadd_rn(__fmul_rn(p, x2), 1.48572235717979e-05f);
    p = __fadd_rn(__fmul_rn(p, x2), 6.37261928875436e-04f);
    p = __fadd_rn(__fmul_rn(p, x2), 4.89352455891786e-03f);
    float num = __fmul_rn(xc, p);
    float q = 1.19825839466702e-06f;
    q = __fadd_rn(__fmul_rn(q, x2), 1.18534705686654e-04f);
    q = __fadd_rn(__fmul_rn(q, x2), 2.26843463243900e-03f);
    q = __fadd_rn(__fmul_rn(q, x2), 4.89352518554385e-03f);
    float r = __fdiv_rn(num, q);
    return (fabsf(x) < 0.0004f) ? x : r;
}

__device__ __forceinline__ float read_scale(int slot) {
    float m = __int_as_float(g_slots[slot]);
    float s = __fdiv_rn(m, QMAXF);
    return fmaxf(s, 1e-12f);
}

// clip(round(v / s), -127, 127), IEEE division + half-even round
__device__ __forceinline__ int q8(float v, float s) {
    float x = __fdiv_rn(v, s);
    x = fminf(fmaxf(x, -127.0f), 127.0f);
    return __float2int_rn(x);
}

__device__ __forceinline__ int pack4(int a, int b, int c, int d) {
    return (a & 0xFF) | ((b & 0xFF) << 8) | ((c & 0xFF) << 16) | ((d & 0xFF) << 24);
}

__device__ __forceinline__ float bias_q(float b, float sb) {
    float r = rintf(__fdiv_rn(b, sb));
    r = fminf(fmaxf(r, -128.0f), 127.0f);
    return __fmul_rn(r, sb);
}

__device__ __forceinline__ void warp_max_atomic(float v, int slot) {
    #pragma unroll
    for (int off = 16; off > 0; off >>= 1)
        v = fmaxf(v, __shfl_xor_sync(0xffffffffu, v, off));
    if ((threadIdx.x & 31) == 0)
        atomicMax(&g_slots[slot], __float_as_int(v));  // v >= 0 -> bits monotone
}

// ---------------------------------------------------------------------------
// 0) zero slots, counter, presence bytes
__global__ void k_init() {
    int i = blockIdx.x * blockDim.x + threadIdx.x;
    if (i < 8) g_slots[i] = 0;
    if (i == 8) g_cnt = 0;
    if (i < NCODE) g_present[i] = 0;
}

// 1) global max of |concat(z,t)|  -> slot 0
__global__ void k_input_max(const float* __restrict__ z, const float* __restrict__ t, int n) {
    float m = 0.0f;
    for (int i = blockIdx.x * blockDim.x + threadIdx.x; i < n; i += gridDim.x * blockDim.x)
        m = fmaxf(m, fmaxf(fabsf(z[i]), fabsf(t[i])));
    warp_max_atomic(m, 0);
}

// 2) weight quantization + packing (blockIdx.x = layer 0..6)
__global__ void k_weight_prep(const float* __restrict__ W1,
                              const float* __restrict__ W2, const float* __restrict__ W3,
                              const float* __restrict__ W4, const float* __restrict__ W5,
                              const float* __restrict__ W6, const float* __restrict__ Wout) {
    int l = blockIdx.x;
    const float* W;
    int cnt;
    if (l == 0)      { W = W1;   cnt = HID * 2; }
    else if (l == 6) { W = Wout; cnt = 2 * HID; }
    else {
        const float* Ws_[5] = {W2, W3, W4, W5, W6};
        W = Ws_[l - 1]; cnt = HID * HID;
    }

    __shared__ float red[256];
    float m = 0.0f;
    for (int i = threadIdx.x; i < cnt; i += 256) m = fmaxf(m, fabsf(W[i]));
    red[threadIdx.x] = m;
    __syncthreads();
    for (int s = 128; s > 0; s >>= 1) {
        if (threadIdx.x < s) red[threadIdx.x] = fmaxf(red[threadIdx.x], red[threadIdx.x + s]);
        __syncthreads();
    }
    __shared__ float s_sw;
    if (threadIdx.x == 0) {
        float sw = fmaxf(__fdiv_rn(red[0], QMAXF), 1e-12f);
        g_sw[l] = sw;
        s_sw = sw;
    }
    __syncthreads();
    float sw = s_sw;

    if (l == 0) {
        for (int i = threadIdx.x; i < HID * 2; i += 256)
            g_W1i[i] = q8(W[i], sw);
    } else if (l == 6) {
        for (int w = threadIdx.x; w < 2 * KG; w += 256) {
            int o = w / KG, kg = w % KG;
            int base = o * HID + kg * 4;
            g_Wpo[o][kg] = pack4(q8(W[base + 0], sw), q8(W[base + 1], sw),
                                 q8(W[base + 2], sw), q8(W[base + 3], sw));
        }
    } else {
        for (int w = threadIdx.x; w < KG * 104; w += 256) {
            int kg = w / 104, c = w % 104;
            int p = 0;
            if (c < HID) {
                int base = c * HID + kg * 4;
                p = pack4(q8(W[base + 0], sw), q8(W[base + 1], sw),
                          q8(W[base + 2], sw), q8(W[base + 3], sw));
            }
            g_Wp[l - 1][kg][c] = p;
        }
    }
}

// 3) per-row code + presence mark
__global__ void k_code(const float* __restrict__ z, const float* __restrict__ t, int n) {
    int i = blockIdx.x * blockDim.x + threadIdx.x;
    if (i >= n) return;
    float sx = read_scale(0);
    int zi = q8(z[i], sx);
    int ti = q8(t[i], sx);
    int c = (zi + 127) * 255 + (ti + 127);
    g_code[i] = c;
    g_present[c] = 1;
}

// 4) compact present codes into a work list (order arbitrary; results invariant)
__global__ void k_compact() {
    int c = blockIdx.x * blockDim.x + threadIdx.x;
    if (c >= NCODE) return;
    if (g_present[c]) {
        int j = atomicAdd(&g_cnt, 1);
        g_list[j] = c;
        g_inv[c] = j;
    }
}

// 5) layer 1 on distinct codes: 25 threads per row, 4 outputs each
__global__ void k_layer1c(const float* __restrict__ b1) {
    __shared__ int   Wls[HID * 2];
    __shared__ float bls[HID];
    __shared__ float s_sb;

    int tid = threadIdx.x;
    if (tid == 0) s_sb = __fmul_rn(read_scale(0), g_sw[0]);
    if (tid < HID * 2) Wls[tid] = g_W1i[tid];
    __syncthreads();
    float sb = s_sb;
    if (tid < HID) bls[tid] = bias_q(b1[tid], sb);
    __syncthreads();

    int cnt = g_cnt;
    int idx = blockIdx.x * blockDim.x + tid;
    int row = idx / 25;
    int og  = idx % 25;
    float vmax = 0.0f;
    if (row < cnt) {
        int c  = g_list[row];
        int zi = c / 255 - 127;
        int ti = c % 255 - 127;
        float4 hv;
        float* hp = &hv.x;
        #pragma unroll
        for (int j = 0; j < 4; j++) {
            int o = og * 4 + j;
            int acc = zi * Wls[o * 2] + ti * Wls[o * 2 + 1];
            float y = (float)acc * sb + bls[o];
            float h = xla_tanh(y);
            hp[j] = h;
            vmax = fmaxf(vmax, fabsf(h));
        }
        ((float4*)(g_hA + (size_t)row * HID))[og] = hv;
    }
    warp_max_atomic(vmax, 1);
}

// 6) hidden layer on distinct rows: dp4a GEMM 128x100 (K=100), tanh, max.
__global__ void __launch_bounds__(416, 2)
k_hidden(const float* __restrict__ bias, int lidx, int dir) {
    int cnt = g_cnt;
    size_t row0 = (size_t)blockIdx.x * 128;
    if (row0 >= (size_t)cnt) return;

    const float* hin  = dir ? g_hB : g_hA;
    float*       hout = dir ? g_hA : g_hB;

    __shared__ __align__(16) int Xs[KG][128];
    __shared__ __align__(16) int Ws[KG][104];
    __shared__ float bqs[104];

    int tid = threadIdx.x;

    float sx = read_scale(lidx);
    float sw = g_sw[lidx];
    float sb = __fmul_rn(sx, sw);

    const float4* src = (const float4*)(hin + row0 * HID);
    for (int w = tid; w < 128 * KG; w += 416) {
        int r = w / KG, kg = w % KG;
        int p = 0;
        if (row0 + (size_t)r < (size_t)cnt) {
            float4 v = src[r * KG + kg];
            p = pack4(q8(v.x, sx), q8(v.y, sx), q8(v.z, sx), q8(v.w, sx));
        }
        Xs[kg][r] = p;
    }
    const int* wp = &g_Wp[lidx - 1][0][0];
    for (int w = tid; w < KG * 104; w += 416)
        ((int*)Ws)[w] = wp[w];
    if (tid < 104) {
        float bq = 0.0f;
        if (tid < HID) bq = bias_q(bias[tid], sb);
        bqs[tid] = bq;
    }
    __syncthreads();

    int cg = tid % 13, rg = tid / 13;
    int c0 = cg * 8, r0 = rg * 4;

    int acc[4][8];
    #pragma unroll
    for (int r = 0; r < 4; r++)
        #pragma unroll
        for (int c = 0; c < 8; c++) acc[r][c] = 0;

    for (int kg = 0; kg < KG; kg++) {
        int4 xv = *(const int4*)&Xs[kg][r0];
        int4 w0 = *(const int4*)&Ws[kg][c0];
        int4 w1 = *(const int4*)&Ws[kg][c0 + 4];
        int xr[4] = {xv.x, xv.y, xv.z, xv.w};
        int wr[8] = {w0.x, w0.y, w0.z, w0.w, w1.x, w1.y, w1.z, w1.w};
        #pragma unroll
        for (int r = 0; r < 4; r++)
            #pragma unroll
            for (int c = 0; c < 8; c++)
                acc[r][c] = __dp4a(xr[r], wr[c], acc[r][c]);
    }

    int nvalid = (c0 + 8 <= HID) ? 8 : 4;
    float vmax = 0.0f;
    #pragma unroll
    for (int r = 0; r < 4; r++) {
        size_t row = row0 + (size_t)(r0 + r);
        float o[8];
        #pragma unroll
        for (int c = 0; c < 8; c++) {
            float y = (float)acc[r][c] * sb + bqs[c0 + c];
            o[c] = xla_tanh(y);
        }
        if (row < (size_t)cnt) {
            #pragma unroll
            for (int c = 0; c < 8; c++)
                if (c < nvalid) vmax = fmaxf(vmax, fabsf(o[c]));
            float* dst = hout + row * HID + c0;
            *(float4*)dst = make_float4(o[0], o[1], o[2], o[3]);
            if (nvalid == 8)
                *(float4*)(dst + 4) = make_float4(o[4], o[5], o[6], o[7]);
        }
    }
    warp_max_atomic(vmax, lidx + 1);
}

// 7) output layer on distinct rows -> table2
__global__ void k_out(const float* __restrict__ bout, int dir) {
    int cnt = g_cnt;
    size_t row0 = (size_t)blockIdx.x * 64;
    if (row0 >= (size_t)cnt) return;

    const float* hin = dir ? g_hB : g_hA;
    __shared__ int Xs[KG][64];
    __shared__ float s_bq[2];

    int tid = threadIdx.x;
    float sx = read_scale(6);
    float sw = g_sw[6];
    float sb = __fmul_rn(sx, sw);

    const float4* src = (const float4*)(hin + row0 * HID);
    for (int w = tid; w < 64 * KG; w += 256) {
        int r = w / KG, kg = w % KG;
        int p = 0;
        if (row0 + (size_t)r < (size_t)cnt) {
            float4 v = src[r * KG + kg];
            p = pack4(q8(v.x, sx), q8(v.y, sx), q8(v.z, sx), q8(v.w, sx));
        }
        Xs[kg][r] = p;
    }
    if (tid < 2) s_bq[tid] = bias_q(bout[tid], sb);
    __syncthreads();

    if (tid < 128) {
        int r = tid >> 1, o = tid & 1;
        size_t row = row0 + (size_t)r;
        if (row < (size_t)cnt) {
            int acc = 0;
            #pragma unroll
            for (int kg = 0; kg < KG; kg++)
                acc = __dp4a(Xs[kg][r], g_Wpo[o][kg], acc);
            g_table2[row * 2 + o] = (float)acc * sb + s_bq[o];
        }
    }
}

// 8) gather per-row results
__global__ void k_gather(float* __restrict__ out, int n) {
    int i = blockIdx.x * blockDim.x + threadIdx.x;
    if (i >= n) return;
    int j = g_inv[g_code[i]];
    ((float2*)out)[i] = ((const float2*)g_table2)[j];
}

// ---------------------------------------------------------------------------

extern "C" void kernel_launch(void* const* d_in, const int* in_sizes, int n_in,
                              void* d_out, int out_size) {
    const float* z    = (const float*)d_in[0];
    const float* t    = (const float*)d_in[1];
    const float* W1   = (const float*)d_in[2];
    const float* b1   = (const float*)d_in[3];
    const float* W2   = (const float*)d_in[4];
    const float* b2   = (const float*)d_in[5];
    const float* W3   = (const float*)d_in[6];
    const float* b3   = (const float*)d_in[7];
    const float* W4   = (const float*)d_in[8];
    const float* b4   = (const float*)d_in[9];
    const float* W5   = (const float*)d_in[10];
    const float* b5   = (const float*)d_in[11];
    const float* W6   = (const float*)d_in[12];
    const float* b6   = (const float*)d_in[13];
    const float* Wout = (const float*)d_in[14];
    const float* bout = (const float*)d_in[15];
    int n = in_sizes[0];

    k_init<<<(NCODE + 255) / 256, 256>>>();
    k_input_max<<<512, 256>>>(z, t, n);
    k_weight_prep<<<7, 256>>>(W1, W2, W3, W4, W5, W6, Wout);
    k_code<<<(n + 255) / 256, 256>>>(z, t, n);
    k_compact<<<(NCODE + 255) / 256, 256>>>();

    int l1_blocks = (NCODE * 25 + 255) / 256;
    k_layer1c<<<l1_blocks, 256>>>(b1);

    int hblocks = (NCODE + 127) / 128;
    k_hidden<<<hblocks, 416>>>(b2, 1, 0);   // A -> B
    k_hidden<<<hblocks, 416>>>(b3, 2, 1);   // B -> A
    k_hidden<<<hblocks, 416>>>(b4, 3, 0);   // A -> B
    k_hidden<<<hblocks, 416>>>(b5, 4, 1);   // B -> A
    k_hidden<<<hblocks, 416>>>(b6, 5, 0);   // A -> B

    int oblocks = (NCODE + 63) / 64;
    k_out<<<oblocks, 256>>>(bout, 1);       // read B

    k_gather<<<(n + 255) / 256, 256>>>((float*)d_out, n);
}

// round 5
// speedup vs baseline: 6.7006x; 1.3881x over previous
#include <cuda_runtime.h>
#include <math.h>

// ---------------------------------------------------------------------------
// QuantPINN: dedup to <=65025 distinct int8 input pairs, then run the whole
// 7-layer quantized MLP in ONE persistent kernel with software grid barriers.
// Exact-integer dp4a GEMM; IEEE-division quantization (fast mul path with
// exact-div fallback, verified bit-identical); XLA rational tanh.
// Launches: k_init -> k_prep (input max | weight quant) -> k_mega.
// ---------------------------------------------------------------------------

#define N_MAX   262144
#define HID     100
#define KG      25          // 100 / 4 int8 per packed word
#define QMAXF   127.0f
#define NCODE   65025       // 255 * 255
#define MAXROW  65152       // NCODE rounded up to 128
#define NBLK    288         // 2 blocks/SM x 148 SMs = 296 >= 288 -> co-resident
#define NTHR    416         // 13 warps
#define GSTRIDE (NBLK * NTHR)

// Activation ping-pong for distinct rows (L2-resident: 26MB each)
__device__ float g_hA[MAXROW * HID];
__device__ float g_hB[MAXROW * HID];
__device__ int   g_Wp[5][KG][104];   // hidden weights packed, out padded to 104
__device__ int   g_W1i[HID * 2];     // layer1 integer weights
__device__ int   g_Wpo[2][KG];       // output layer packed weights
__device__ float g_sw[7];            // weight scales
__device__ int   g_slots[8];         // activation |max| as float bits
__device__ int   g_code[N_MAX];
__device__ unsigned char g_present[NCODE];
__device__ int   g_list[NCODE];
__device__ int   g_inv[NCODE];
__device__ int   g_cnt;
__device__ float g_table2[NCODE * 2];
__device__ int   g_bar_cnt;
__device__ int   g_bar_sense;

// ---------------------------------------------------------------------------
__device__ __forceinline__ float xla_tanh(float x) {
    const float kMax = 7.90531110763549805f;
    float xc = fmaxf(-kMax, fminf(x, kMax));
    float x2 = __fmul_rn(xc, xc);
    float p = -2.76076847742355e-16f;
    p = __fadd_rn(__fmul_rn(p, x2), 2.00018790482477e-13f);
    p = __fadd_rn(__fmul_rn(p, x2), -8.60467152213735e-11f);
    p = __fadd_rn(__fmul_rn(p, x2), 5.12229709037114e-08f);
    p = __fadd_rn(__fmul_rn(p, x2), 1.48572235717979e-05f);
    p = __fadd_rn(__fmul_rn(p, x2), 6.37261928875436e-04f);
    p = __fadd_rn(__fmul_rn(p, x2), 4.89352455891786e-03f);
    float num = __fmul_rn(xc, p);
    float q = 1.19825839466702e-06f;
    q = __fadd_rn(__fmul_rn(q, x2), 1.18534705686654e-04f);
    q = __fadd_rn(__fmul_rn(q, x2), 2.26843463243900e-03f);
    q = __fadd_rn(__fmul_rn(q, x2), 4.89352518554385e-03f);
    float r = __fdiv_rn(num, q);
    return (fabsf(x) < 0.0004f) ? x : r;
}

__device__ __forceinline__ float read_scale(int slot) {
    float m = __int_as_float(g_slots[slot]);
    float s = __fdiv_rn(m, QMAXF);
    return fmaxf(s, 1e-12f);
}

// exact: clip(round(v/s), -127, 127), IEEE division + half-even round
__device__ __forceinline__ int q8(float v, float s) {
    float x = __fdiv_rn(v, s);
    x = fminf(fmaxf(x, -127.0f), 127.0f);
    return __float2int_rn(x);
}

// fast: mul by fl(1/s); exact divide only within ~2ulp of a .5 boundary
__device__ __forceinline__ int q8f(float v, float s, float inv) {
    float r = __fmul_rn(v, inv);
    float rr = rintf(r);
    float d = fabsf(__fadd_rn(r, -rr));
    if (fabsf(d - 0.5f) < (4e-7f * fabsf(r) + 1e-9f))
        r = __fdiv_rn(v, s);
    r = fminf(fmaxf(r, -127.0f), 127.0f);
    return __float2int_rn(r);
}

__device__ __forceinline__ int pack4(int a, int b, int c, int d) {
    return (a & 0xFF) | ((b & 0xFF) << 8) | ((c & 0xFF) << 16) | ((d & 0xFF) << 24);
}

__device__ __forceinline__ float bias_q(float b, float sb) {
    float r = rintf(__fdiv_rn(b, sb));
    r = fminf(fmaxf(r, -128.0f), 127.0f);
    return __fmul_rn(r, sb);
}

// sense-reversing grid barrier; ALL NBLK blocks are co-resident by construction
__device__ __forceinline__ void grid_bar(int& sense) {
    int s = sense ^ 1;
    __threadfence();
    __syncthreads();
    if (threadIdx.x == 0) {
        int a = atomicAdd(&g_bar_cnt, 1);
        if (a == NBLK - 1) {
            atomicExch(&g_bar_cnt, 0);
            __threadfence();
            atomicExch(&g_bar_sense, s);
        } else {
            while (atomicAdd(&g_bar_sense, 0) != s) __nanosleep(128);
        }
    }
    __syncthreads();
    __threadfence();
    sense = s;
}

// block-wide max -> one atomic per block
__device__ __forceinline__ void block_max_atomic(float v, int slot, float* s_red) {
    #pragma unroll
    for (int off = 16; off > 0; off >>= 1)
        v = fmaxf(v, __shfl_xor_sync(0xffffffffu, v, off));
    int w = threadIdx.x >> 5;
    if ((threadIdx.x & 31) == 0) s_red[w] = v;
    __syncthreads();
    if (threadIdx.x == 0) {
        float m = s_red[0];
        #pragma unroll
        for (int i = 1; i < NTHR / 32; i++) m = fmaxf(m, s_red[i]);
        atomicMax(&g_slots[slot], __float_as_int(m));   // m >= 0
    }
    __syncthreads();
}

// ---------------------------------------------------------------------------
// 0) zero slots, counters, barrier state, presence bytes
__global__ void k_init() {
    int i = blockIdx.x * blockDim.x + threadIdx.x;
    if (i < NCODE) g_present[i] = 0;
    if (i < 8) g_slots[i] = 0;
    if (i == 8) g_cnt = 0;
    if (i == 9) g_bar_cnt = 0;
    if (i == 10) g_bar_sense = 0;
}

// 1) blocks 0..255: |max| of concat(z,t) -> slot0 ; blocks 256..262: weight prep
__global__ void k_prep(const float* __restrict__ z, const float* __restrict__ t,
                       const float* __restrict__ W1,
                       const float* __restrict__ W2, const float* __restrict__ W3,
                       const float* __restrict__ W4, const float* __restrict__ W5,
                       const float* __restrict__ W6, const float* __restrict__ Wout,
                       int n) {
    __shared__ float red[256];
    int tid = threadIdx.x;
    int bid = blockIdx.x;

    if (bid < 256) {
        float m = 0.0f;
        for (int i = bid * 256 + tid; i < n; i += 256 * 256)
            m = fmaxf(m, fmaxf(fabsf(z[i]), fabsf(t[i])));
        #pragma unroll
        for (int off = 16; off > 0; off >>= 1)
            m = fmaxf(m, __shfl_xor_sync(0xffffffffu, m, off));
        if ((tid & 31) == 0) red[tid >> 5] = m;
        __syncthreads();
        if (tid == 0) {
            float mm = red[0];
            #pragma unroll
            for (int i = 1; i < 8; i++) mm = fmaxf(mm, red[i]);
            atomicMax(&g_slots[0], __float_as_int(mm));
        }
        return;
    }

    int l = bid - 256;   // 0..6
    const float* W;
    int cnt;
    if (l == 0)      { W = W1;   cnt = HID * 2; }
    else if (l == 6) { W = Wout; cnt = 2 * HID; }
    else {
        const float* Ws_[5] = {W2, W3, W4, W5, W6};
        W = Ws_[l - 1]; cnt = HID * HID;
    }

    float m = 0.0f;
    for (int i = tid; i < cnt; i += 256) m = fmaxf(m, fabsf(W[i]));
    red[tid] = m;
    __syncthreads();
    for (int s = 128; s > 0; s >>= 1) {
        if (tid < s) red[tid] = fmaxf(red[tid], red[tid + s]);
        __syncthreads();
    }
    __shared__ float s_sw;
    if (tid == 0) {
        float sw = fmaxf(__fdiv_rn(red[0], QMAXF), 1e-12f);
        g_sw[l] = sw;
        s_sw = sw;
    }
    __syncthreads();
    float sw = s_sw;

    if (l == 0) {
        for (int i = tid; i < HID * 2; i += 256)
            g_W1i[i] = q8(W[i], sw);
    } else if (l == 6) {
        for (int w = tid; w < 2 * KG; w += 256) {
            int o = w / KG, kg = w % KG;
            int base = o * HID + kg * 4;
            g_Wpo[o][kg] = pack4(q8(W[base + 0], sw), q8(W[base + 1], sw),
                                 q8(W[base + 2], sw), q8(W[base + 3], sw));
        }
    } else {
        for (int w = tid; w < KG * 104; w += 256) {
            int kg = w / 104, c = w % 104;
            int p = 0;
            if (c < HID) {
                int base = c * HID + kg * 4;
                p = pack4(q8(W[base + 0], sw), q8(W[base + 1], sw),
                          q8(W[base + 2], sw), q8(W[base + 3], sw));
            }
            g_Wp[l - 1][kg][c] = p;
        }
    }
}

// ---------------------------------------------------------------------------
// 2) persistent mega-kernel: code -> compact -> layer1 -> 5x hidden -> out -> gather
__global__ void __launch_bounds__(NTHR, 2)
k_mega(const float* __restrict__ z, const float* __restrict__ t,
       const float* __restrict__ b1, const float* __restrict__ b2,
       const float* __restrict__ b3, const float* __restrict__ b4,
       const float* __restrict__ b5, const float* __restrict__ b6,
       const float* __restrict__ bout, float* __restrict__ out, int n) {
    __shared__ __align__(16) int s_Ws[KG][104];
    __shared__ __align__(16) int s_Xs[KG][128];
    __shared__ float s_bqs[104];
    __shared__ float s_red[16];

    int tid  = threadIdx.x;
    int gtid = blockIdx.x * NTHR + tid;
    int sense = 0;

    // ---- P0: per-row codes + presence marks --------------------------------
    {
        float sx = read_scale(0);
        float inv = __fdiv_rn(1.0f, sx);
        for (int i = gtid; i < n; i += GSTRIDE) {
            int zi = q8f(z[i], sx, inv);
            int ti = q8f(t[i], sx, inv);
            int c = (zi + 127) * 255 + (ti + 127);
            g_code[i] = c;
            g_present[c] = 1;
        }
    }
    grid_bar(sense);

    // ---- P1: warp-aggregated compaction ------------------------------------
    {
        int lane = tid & 31;
        unsigned lt = (1u << lane) - 1u;
        int bound = ((NCODE + GSTRIDE - 1) / GSTRIDE) * GSTRIDE;
        for (int c = gtid; c < bound; c += GSTRIDE) {
            bool p = (c < NCODE) && g_present[c];
            unsigned mask = __ballot_sync(0xffffffffu, p);
            int base = 0;
            if (lane == 0 && mask) base = atomicAdd(&g_cnt, __popc(mask));
            base = __shfl_sync(0xffffffffu, base, 0);
            if (p) {
                int j = base + __popc(mask & lt);
                g_list[j] = c;
                g_inv[c] = j;
            }
        }
    }
    grid_bar(sense);
    int cnt = g_cnt;

    // ---- P2: layer 1 on distinct codes --------------------------------------
    {
        float sb = __fmul_rn(read_scale(0), g_sw[0]);
        int* Wls = &s_Ws[0][0];
        if (tid < HID * 2) Wls[tid] = g_W1i[tid];
        if (tid < HID)     s_bqs[tid] = bias_q(b1[tid], sb);
        __syncthreads();

        float vmax = 0.0f;
        int tot = cnt * 25;
        for (int idx = gtid; idx < tot; idx += GSTRIDE) {
            int row = idx / 25;
            int og  = idx - row * 25;
            int c   = g_list[row];
            int hi  = c / 255;
            int zi  = hi - 127;
            int ti  = (c - hi * 255) - 127;
            float4 hv;
            float* hp = &hv.x;
            #pragma unroll
            for (int j = 0; j < 4; j++) {
                int o = og * 4 + j;
                int acc = zi * Wls[o * 2] + ti * Wls[o * 2 + 1];
                float y = (float)acc * sb + s_bqs[o];
                float h = xla_tanh(y);
                hp[j] = h;
                vmax = fmaxf(vmax, fabsf(h));
            }
            ((float4*)(g_hA + (size_t)row * HID))[og] = hv;
        }
        block_max_atomic(vmax, 1, s_red);
    }
    grid_bar(sense);

    // ---- P3..P7: hidden layers 2..6 -----------------------------------------
    {
        const float* biases[5] = {b2, b3, b4, b5, b6};
        int cg = tid % 13, rg = tid / 13;
        int c0 = cg * 8, r0 = rg * 4;
        int nvalid = (c0 + 8 <= HID) ? 8 : 4;
        int ntiles = (cnt + 127) >> 7;

        for (int l = 1; l <= 5; l++) {
            const float* hin  = (l & 1) ? g_hA : g_hB;
            float*       hout = (l & 1) ? g_hB : g_hA;
            const float* bias = biases[l - 1];

            float sx = read_scale(l);
            float inv = __fdiv_rn(1.0f, sx);
            float sb = __fmul_rn(sx, g_sw[l]);

            const int* wp = &g_Wp[l - 1][0][0];
            for (int w = tid; w < KG * 104; w += NTHR)
                ((int*)s_Ws)[w] = wp[w];
            if (tid < 104)
                s_bqs[tid] = (tid < HID) ? bias_q(bias[tid], sb) : 0.0f;
            __syncthreads();

            float vmax = 0.0f;
            for (int tile = blockIdx.x; tile < ntiles; tile += NBLK) {
                size_t row0 = (size_t)tile * 128;
                const float4* src = (const float4*)(hin + row0 * HID);
                for (int w = tid; w < 128 * KG; w += NTHR) {
                    int r = w / KG, kg = w - r * KG;
                    int p = 0;
                    if (row0 + (size_t)r < (size_t)cnt) {
                        float4 v = src[r * KG + kg];
                        p = pack4(q8f(v.x, sx, inv), q8f(v.y, sx, inv),
                                  q8f(v.z, sx, inv), q8f(v.w, sx, inv));
                    }
                    s_Xs[kg][r] = p;
                }
                __syncthreads();

                int acc[4][8];
                #pragma unroll
                for (int r = 0; r < 4; r++)
                    #pragma unroll
                    for (int c = 0; c < 8; c++) acc[r][c] = 0;

                for (int kg = 0; kg < KG; kg++) {
                    int4 xv = *(const int4*)&s_Xs[kg][r0];
                    int4 w0 = *(const int4*)&s_Ws[kg][c0];
                    int4 w1 = *(const int4*)&s_Ws[kg][c0 + 4];
                    int xr[4] = {xv.x, xv.y, xv.z, xv.w};
                    int wr[8] = {w0.x, w0.y, w0.z, w0.w, w1.x, w1.y, w1.z, w1.w};
                    #pragma unroll
                    for (int r = 0; r < 4; r++)
                        #pragma unroll
                        for (int c = 0; c < 8; c++)
                            acc[r][c] = __dp4a(xr[r], wr[c], acc[r][c]);
                }

                #pragma unroll
                for (int r = 0; r < 4; r++) {
                    size_t row = row0 + (size_t)(r0 + r);
                    float o[8];
                    #pragma unroll
                    for (int c = 0; c < 8; c++) {
                        float y = (float)acc[r][c] * sb + s_bqs[c0 + c];
                        o[c] = xla_tanh(y);
                    }
                    if (row < (size_t)cnt) {
                        #pragma unroll
                        for (int c = 0; c < 8; c++)
                            if (c < nvalid) vmax = fmaxf(vmax, fabsf(o[c]));
                        float* dst = hout + row * HID + c0;
                        *(float4*)dst = make_float4(o[0], o[1], o[2], o[3]);
                        if (nvalid == 8)
                            *(float4*)(dst + 4) = make_float4(o[4], o[5], o[6], o[7]);
                    }
                }
                __syncthreads();
            }
            block_max_atomic(vmax, l + 1, s_red);
            grid_bar(sense);
        }
    }

    // ---- P8: output layer -> table ------------------------------------------
    {
        float sx = read_scale(6);
        float inv = __fdiv_rn(1.0f, sx);
        float sb = __fmul_rn(sx, g_sw[6]);
        float bq0 = bias_q(bout[0], sb);
        float bq1 = bias_q(bout[1], sb);
        const float* hin = g_hB;   // h6 lives in B (l=5 odd: A->B)
        int ntiles = (cnt + 127) >> 7;

        for (int tile = blockIdx.x; tile < ntiles; tile += NBLK) {
            size_t row0 = (size_t)tile * 128;
            const float4* src = (const float4*)(hin + row0 * HID);
            for (int w = tid; w < 128 * KG; w += NTHR) {
                int r = w / KG, kg = w - r * KG;
                int p = 0;
                if (row0 + (size_t)r < (size_t)cnt) {
                    float4 v = src[r * KG + kg];
                    p = pack4(q8f(v.x, sx, inv), q8f(v.y, sx, inv),
                              q8f(v.z, sx, inv), q8f(v.w, sx, inv));
                }
                s_Xs[kg][r] = p;
            }
            __syncthreads();

            if (tid < 256) {
                int r = tid >> 1, o = tid & 1;
                size_t row = row0 + (size_t)r;
                if (row < (size_t)cnt) {
                    int acc = 0;
                    #pragma unroll
                    for (int kg = 0; kg < KG; kg++)
                        acc = __dp4a(s_Xs[kg][r], g_Wpo[o][kg], acc);
                    g_table2[row * 2 + o] = (float)acc * sb + (o ? bq1 : bq0);
                }
            }
            __syncthreads();
        }
    }
    grid_bar(sense);

    // ---- P9: gather per input row -------------------------------------------
    for (int i = gtid; i < n; i += GSTRIDE) {
        int j = g_inv[g_code[i]];
        ((float2*)out)[i] = ((const float2*)g_table2)[j];
    }
}

// ---------------------------------------------------------------------------

extern "C" void kernel_launch(void* const* d_in, const int* in_sizes, int n_in,
                              void* d_out, int out_size) {
    const float* z    = (const float*)d_in[0];
    const float* t    = (const float*)d_in[1];
    const float* W1   = (const float*)d_in[2];
    const float* b1   = (const float*)d_in[3];
    const float* W2   = (const float*)d_in[4];
    const float* b2   = (const float*)d_in[5];
    const float* W3   = (const float*)d_in[6];
    const float* b3   = (const float*)d_in[7];
    const float* W4   = (const float*)d_in[8];
    const float* b4   = (const float*)d_in[9];
    const float* W5   = (const float*)d_in[10];
    const float* b5   = (const float*)d_in[11];
    const float* W6   = (const float*)d_in[12];
    const float* b6   = (const float*)d_in[13];
    const float* Wout = (const float*)d_in[14];
    const float* bout = (const float*)d_in[15];
    int n = in_sizes[0];

    k_init<<<256, 256>>>();
    k_prep<<<263, 256>>>(z, t, W1, W2, W3, W4, W5, W6, Wout, n);
    k_mega<<<NBLK, NTHR>>>(z, t, b1, b2, b3, b4, b5, b6, bout, (float*)d_out, n);
}

// round 6
// speedup vs baseline: 8.1657x; 1.2187x over previous
#include <cuda_runtime.h>
#include <math.h>

// ---------------------------------------------------------------------------
// QuantPINN: dedup to distinct int8 input pairs, whole 7-layer quantized MLP
// in ONE persistent kernel with software grid barriers. Hidden GEMMs on
// tensor cores (mma.sync m16n8k32 s8, K zero-padded 100->128: bit-identical
// to dp4a). Numerics frozen: IEEE-div quantization (fast path), XLA tanh.
// Launches: k_prep (input max | weight quant | state reset) -> k_mega.
// ---------------------------------------------------------------------------

#define N_MAX   262144
#define HID     100
#define KG      25          // 100 / 4 int8 per packed word
#define KGP     32          // K padded to 128 int8
#define QMAXF   127.0f
#define NCODE   65025       // 255 * 255
#define MAXROW  65152
#define NBLK    288         // 2/SM x 148 SMs = 296 >= 288 -> co-resident
#define NTHR    416         // 13 warps
#define GSTRIDE (NBLK * NTHR)
#define XS_STR  132         // Xs row stride (words): conflict-free A frags

__device__ float g_hA[MAXROW * HID];
__device__ float g_hB[MAXROW * HID];
__device__ int   g_Wp[5][KGP][104];  // hidden weights packed, K+out padded
__device__ int   g_W1i[HID * 2];
__device__ int   g_Wpo[2][KG];
__device__ float g_sw[7];
__device__ int   g_slots[8];         // activation |max| bits (replay-idempotent)
__device__ int   g_code[N_MAX];
__device__ int   g_present[NCODE];   // generation-stamped (no per-run clear)
__device__ int   g_gen;
__device__ int   g_list[NCODE];
__device__ int   g_inv[NCODE];
__device__ int   g_cnt;
__device__ float g_table2[NCODE * 2];
__device__ int   g_bar_cnt;
__device__ int   g_bar_sense;

// ---------------------------------------------------------------------------
__device__ __forceinline__ float xla_tanh(float x) {
    const float kMax = 7.90531110763549805f;
    float xc = fmaxf(-kMax, fminf(x, kMax));
    float x2 = __fmul_rn(xc, xc);
    float p = -2.76076847742355e-16f;
    p = __fadd_rn(__fmul_rn(p, x2), 2.00018790482477e-13f);
    p = __fadd_rn(__fmul_rn(p, x2), -8.60467152213735e-11f);
    p = __fadd_rn(__fmul_rn(p, x2), 5.12229709037114e-08f);
    p = __fadd_rn(__fmul_rn(p, x2), 1.48572235717979e-05f);
    p = __fadd_rn(__fmul_rn(p, x2), 6.37261928875436e-04f);
    p = __fadd_rn(__fmul_rn(p, x2), 4.89352455891786e-03f);
    float num = __fmul_rn(xc, p);
    float q = 1.19825839466702e-06f;
    q = __fadd_rn(__fmul_rn(q, x2), 1.18534705686654e-04f);
    q = __fadd_rn(__fmul_rn(q, x2), 2.26843463243900e-03f);
    q = __fadd_rn(__fmul_rn(q, x2), 4.89352518554385e-03f);
    float r = __fdiv_rn(num, q);
    return (fabsf(x) < 0.0004f) ? x : r;
}

__device__ __forceinline__ float read_scale(int slot) {
    float m = __int_as_float(g_slots[slot]);
    float s = __fdiv_rn(m, QMAXF);
    return fmaxf(s, 1e-12f);
}

__device__ __forceinline__ int q8(float v, float s) {
    float x = __fdiv_rn(v, s);
    x = fminf(fmaxf(x, -127.0f), 127.0f);
    return __float2int_rn(x);
}

__device__ __forceinline__ int q8f(float v, float s, float inv) {
    float r = __fmul_rn(v, inv);
    float rr = rintf(r);
    float d = fabsf(__fadd_rn(r, -rr));
    if (fabsf(d - 0.5f) < (4e-7f * fabsf(r) + 1e-9f))
        r = __fdiv_rn(v, s);
    r = fminf(fmaxf(r, -127.0f), 127.0f);
    return __float2int_rn(r);
}

__device__ __forceinline__ int pack4(int a, int b, int c, int d) {
    return (a & 0xFF) | ((b & 0xFF) << 8) | ((c & 0xFF) << 16) | ((d & 0xFF) << 24);
}

__device__ __forceinline__ float bias_q(float b, float sb) {
    float r = rintf(__fdiv_rn(b, sb));
    r = fminf(fmaxf(r, -128.0f), 127.0f);
    return __fmul_rn(r, sb);
}

__device__ __forceinline__ void mma_s8(int& d0, int& d1, int& d2, int& d3,
                                       int a0, int a1, int a2, int a3,
                                       int b0, int b1) {
    asm volatile(
        "mma.sync.aligned.m16n8k32.row.col.s32.s8.s8.s32 "
        "{%0,%1,%2,%3}, {%4,%5,%6,%7}, {%8,%9}, {%0,%1,%2,%3};"
        : "+r"(d0), "+r"(d1), "+r"(d2), "+r"(d3)
        : "r"(a0), "r"(a1), "r"(a2), "r"(a3), "r"(b0), "r"(b1));
}

__device__ __forceinline__ void grid_bar(int& sense) {
    int s = sense ^ 1;
    __threadfence();
    __syncthreads();
    if (threadIdx.x == 0) {
        int a = atomicAdd(&g_bar_cnt, 1);
        if (a == NBLK - 1) {
            atomicExch(&g_bar_cnt, 0);
            __threadfence();
            atomicExch(&g_bar_sense, s);
        } else {
            while (atomicAdd(&g_bar_sense, 0) != s) __nanosleep(128);
        }
    }
    __syncthreads();
    __threadfence();
    sense = s;
}

__device__ __forceinline__ void block_max_atomic(float v, int slot, float* s_red) {
    #pragma unroll
    for (int off = 16; off > 0; off >>= 1)
        v = fmaxf(v, __shfl_xor_sync(0xffffffffu, v, off));
    int w = threadIdx.x >> 5;
    if ((threadIdx.x & 31) == 0) s_red[w] = v;
    __syncthreads();
    if (threadIdx.x == 0) {
        float m = s_red[0];
        #pragma unroll
        for (int i = 1; i < NTHR / 32; i++) m = fmaxf(m, s_red[i]);
        atomicMax(&g_slots[slot], __float_as_int(m));
    }
    __syncthreads();
}

// ---------------------------------------------------------------------------
// blocks 0..255: input |max| -> slot0; 256..262: weight prep; 263: state reset
__global__ void k_prep(const float* __restrict__ z, const float* __restrict__ t,
                       const float* __restrict__ W1,
                       const float* __restrict__ W2, const float* __restrict__ W3,
                       const float* __restrict__ W4, const float* __restrict__ W5,
                       const float* __restrict__ W6, const float* __restrict__ Wout,
                       int n) {
    __shared__ float red[256];
    int tid = threadIdx.x;
    int bid = blockIdx.x;

    if (bid < 256) {
        float m = 0.0f;
        for (int i = bid * 256 + tid; i < n; i += 256 * 256)
            m = fmaxf(m, fmaxf(fabsf(z[i]), fabsf(t[i])));
        #pragma unroll
        for (int off = 16; off > 0; off >>= 1)
            m = fmaxf(m, __shfl_xor_sync(0xffffffffu, m, off));
        if ((tid & 31) == 0) red[tid >> 5] = m;
        __syncthreads();
        if (tid == 0) {
            float mm = red[0];
            #pragma unroll
            for (int i = 1; i < 8; i++) mm = fmaxf(mm, red[i]);
            atomicMax(&g_slots[0], __float_as_int(mm));
        }
        return;
    }
    if (bid == 263) {
        if (tid == 0) {
            g_cnt = 0;
            g_bar_cnt = 0;
            g_bar_sense = 0;
            g_gen = g_gen + 1;
        }
        return;
    }

    int l = bid - 256;   // 0..6
    const float* W;
    int cnt;
    if (l == 0)      { W = W1;   cnt = HID * 2; }
    else if (l == 6) { W = Wout; cnt = 2 * HID; }
    else {
        const float* Ws_[5] = {W2, W3, W4, W5, W6};
        W = Ws_[l - 1]; cnt = HID * HID;
    }

    float m = 0.0f;
    for (int i = tid; i < cnt; i += 256) m = fmaxf(m, fabsf(W[i]));
    red[tid] = m;
    __syncthreads();
    for (int s = 128; s > 0; s >>= 1) {
        if (tid < s) red[tid] = fmaxf(red[tid], red[tid + s]);
        __syncthreads();
    }
    __shared__ float s_sw;
    if (tid == 0) {
        float sw = fmaxf(__fdiv_rn(red[0], QMAXF), 1e-12f);
        g_sw[l] = sw;
        s_sw = sw;
    }
    __syncthreads();
    float sw = s_sw;

    if (l == 0) {
        for (int i = tid; i < HID * 2; i += 256)
            g_W1i[i] = q8(W[i], sw);
    } else if (l == 6) {
        for (int w = tid; w < 2 * KG; w += 256) {
            int o = w / KG, kg = w % KG;
            int base = o * HID + kg * 4;
            g_Wpo[o][kg] = pack4(q8(W[base + 0], sw), q8(W[base + 1], sw),
                                 q8(W[base + 2], sw), q8(W[base + 3], sw));
        }
    } else {
        for (int w = tid; w < KGP * 104; w += 256) {
            int kg = w / 104, c = w % 104;
            int p = 0;
            if (kg < KG && c < HID) {
                int base = c * HID + kg * 4;
                p = pack4(q8(W[base + 0], sw), q8(W[base + 1], sw),
                          q8(W[base + 2], sw), q8(W[base + 3], sw));
            }
            g_Wp[l - 1][kg][c] = p;
        }
    }
}

// ---------------------------------------------------------------------------
__global__ void __launch_bounds__(NTHR, 2)
k_mega(const float* __restrict__ z, const float* __restrict__ t,
       const float* __restrict__ b1, const float* __restrict__ b2,
       const float* __restrict__ b3, const float* __restrict__ b4,
       const float* __restrict__ b5, const float* __restrict__ b6,
       const float* __restrict__ bout, float* __restrict__ out, int n) {
    __shared__ __align__(16) int s_Ws[KGP][104];
    __shared__ __align__(16) int s_Xs[KGP][XS_STR];
    __shared__ float s_bqs[104];
    __shared__ float s_red[16];

    int tid  = threadIdx.x;
    int gtid = blockIdx.x * NTHR + tid;
    int sense = 0;
    int gen = g_gen;

    // ---- P0: per-row codes + presence marks --------------------------------
    {
        float sx = read_scale(0);
        float inv = __fdiv_rn(1.0f, sx);
        for (int i = gtid; i < n; i += GSTRIDE) {
            int zi = q8f(z[i], sx, inv);
            int ti = q8f(t[i], sx, inv);
            int c = (zi + 127) * 255 + (ti + 127);
            g_code[i] = c;
            g_present[c] = gen;
        }
    }
    grid_bar(sense);

    // ---- P1: warp-aggregated compaction ------------------------------------
    {
        int lane = tid & 31;
        unsigned lt = (1u << lane) - 1u;
        int bound = ((NCODE + GSTRIDE - 1) / GSTRIDE) * GSTRIDE;
        for (int c = gtid; c < bound; c += GSTRIDE) {
            bool p = (c < NCODE) && (g_present[c] == gen);
            unsigned mask = __ballot_sync(0xffffffffu, p);
            int base = 0;
            if (lane == 0 && mask) base = atomicAdd(&g_cnt, __popc(mask));
            base = __shfl_sync(0xffffffffu, base, 0);
            if (p) {
                int j = base + __popc(mask & lt);
                g_list[j] = c;
                g_inv[c] = j;
            }
        }
    }
    grid_bar(sense);
    int cnt = g_cnt;

    // ---- P2: layer 1 on distinct codes --------------------------------------
    {
        float sb = __fmul_rn(read_scale(0), g_sw[0]);
        int* Wls = &s_Ws[0][0];
        if (tid < HID * 2) Wls[tid] = g_W1i[tid];
        if (tid < HID)     s_bqs[tid] = bias_q(b1[tid], sb);
        __syncthreads();

        float vmax = 0.0f;
        int tot = cnt * 25;
        for (int idx = gtid; idx < tot; idx += GSTRIDE) {
            int row = idx / 25;
            int og  = idx - row * 25;
            int c   = g_list[row];
            int hi  = c / 255;
            int zi  = hi - 127;
            int ti  = (c - hi * 255) - 127;
            float4 hv;
            float* hp = &hv.x;
            #pragma unroll
            for (int j = 0; j < 4; j++) {
                int o = og * 4 + j;
                int acc = zi * Wls[o * 2] + ti * Wls[o * 2 + 1];
                float y = (float)acc * sb + s_bqs[o];
                float h = xla_tanh(y);
                hp[j] = h;
                vmax = fmaxf(vmax, fabsf(h));
            }
            ((float4*)(g_hA + (size_t)row * HID))[og] = hv;
        }
        block_max_atomic(vmax, 1, s_red);
    }
    grid_bar(sense);

    // ---- P3..P7: hidden layers 2..6 on tensor cores --------------------------
    {
        const float* biases[5] = {b2, b3, b4, b5, b6};
        int lane = tid & 31, wrp = tid >> 5;    // 13 warps; warp -> 8 columns
        int g = lane >> 2, tg = lane & 3;
        int cA = (wrp << 3) + (tg << 1);        // even column pair base
        bool colok = (cA < HID);
        int ntiles = (cnt + 127) >> 7;

        for (int l = 1; l <= 5; l++) {
            const float* hin  = (l & 1) ? g_hA : g_hB;
            float*       hout = (l & 1) ? g_hB : g_hA;
            const float* bias = biases[l - 1];

            float sx = read_scale(l);
            float inv = __fdiv_rn(1.0f, sx);
            float sb = __fmul_rn(sx, g_sw[l]);

            const int* wp = &g_Wp[l - 1][0][0];
            for (int w = tid; w < KGP * 104; w += NTHR)
                ((int*)s_Ws)[w] = wp[w];
            if (tid < 104)
                s_bqs[tid] = (tid < HID) ? bias_q(bias[tid], sb) : 0.0f;
            __syncthreads();

            // B fragments: constant for the whole layer
            int bf0[4], bf1[4];
            #pragma unroll
            for (int kc = 0; kc < 4; kc++) {
                bf0[kc] = s_Ws[8 * kc + tg][(wrp << 3) + g];
                bf1[kc] = s_Ws[8 * kc + tg + 4][(wrp << 3) + g];
            }

            float vmax = 0.0f;
            float bqA = colok ? s_bqs[cA] : 0.0f;
            float bqB = colok ? s_bqs[cA + 1] : 0.0f;

            for (int tile = blockIdx.x; tile < ntiles; tile += NBLK) {
                size_t row0 = (size_t)tile * 128;
                const float4* src = (const float4*)(hin + row0 * HID);
                for (int w = tid; w < 128 * KGP; w += NTHR) {
                    int r = w >> 5, kg = w & 31;
                    int p = 0;
                    if (kg < KG && row0 + (size_t)r < (size_t)cnt) {
                        float4 v = src[r * KG + kg];
                        p = pack4(q8f(v.x, sx, inv), q8f(v.y, sx, inv),
                                  q8f(v.z, sx, inv), q8f(v.w, sx, inv));
                    }
                    s_Xs[kg][r] = p;
                }
                __syncthreads();

                #pragma unroll
                for (int mt = 0; mt < 8; mt++) {
                    int d0 = 0, d1 = 0, d2 = 0, d3 = 0;
                    int rbase = (mt << 4) + g;
                    #pragma unroll
                    for (int kc = 0; kc < 4; kc++) {
                        int a0 = s_Xs[8 * kc + tg][rbase];
                        int a1 = s_Xs[8 * kc + tg][rbase + 8];
                        int a2 = s_Xs[8 * kc + tg + 4][rbase];
                        int a3 = s_Xs[8 * kc + tg + 4][rbase + 8];
                        mma_s8(d0, d1, d2, d3, a0, a1, a2, a3, bf0[kc], bf1[kc]);
                    }
                    if (colok) {
                        size_t rA = row0 + (size_t)rbase;
                        if (rA < (size_t)cnt) {
                            float y0 = (float)d0 * sb + bqA;
                            float y1 = (float)d1 * sb + bqB;
                            float h0 = xla_tanh(y0);
                            float h1 = xla_tanh(y1);
                            vmax = fmaxf(vmax, fmaxf(fabsf(h0), fabsf(h1)));
                            *(float2*)(hout + rA * HID + cA) = make_float2(h0, h1);
                        }
                        size_t rB = rA + 8;
                        if (rB < (size_t)cnt) {
                            float y2 = (float)d2 * sb + bqA;
                            float y3 = (float)d3 * sb + bqB;
                            float h2 = xla_tanh(y2);
                            float h3 = xla_tanh(y3);
                            vmax = fmaxf(vmax, fmaxf(fabsf(h2), fabsf(h3)));
                            *(float2*)(hout + rB * HID + cA) = make_float2(h2, h3);
                        }
                    }
                }
                __syncthreads();
            }
            block_max_atomic(vmax, l + 1, s_red);
            grid_bar(sense);
        }
    }

    // ---- P8: output layer -> table ------------------------------------------
    {
        float sx = read_scale(6);
        float inv = __fdiv_rn(1.0f, sx);
        float sb = __fmul_rn(sx, g_sw[6]);
        float bq0 = bias_q(bout[0], sb);
        float bq1 = bias_q(bout[1], sb);
        const float* hin = g_hB;   // h6 in B (l=5 odd: A->B)
        int ntiles = (cnt + 127) >> 7;

        for (int tile = blockIdx.x; tile < ntiles; tile += NBLK) {
            size_t row0 = (size_t)tile * 128;
            const float4* src = (const float4*)(hin + row0 * HID);
            for (int w = tid; w < 128 * KG; w += NTHR) {
                int r = w / KG, kg = w - r * KG;
                int p = 0;
                if (row0 + (size_t)r < (size_t)cnt) {
                    float4 v = src[r * KG + kg];
                    p = pack4(q8f(v.x, sx, inv), q8f(v.y, sx, inv),
                              q8f(v.z, sx, inv), q8f(v.w, sx, inv));
                }
                s_Xs[kg][r] = p;
            }
            __syncthreads();

            if (tid < 256) {
                int r = tid >> 1, o = tid & 1;
                size_t row = row0 + (size_t)r;
                if (row < (size_t)cnt) {
                    int acc = 0;
                    #pragma unroll
                    for (int kg = 0; kg < KG; kg++)
                        acc = __dp4a(s_Xs[kg][r], g_Wpo[o][kg], acc);
                    g_table2[row * 2 + o] = (float)acc * sb + (o ? bq1 : bq0);
                }
            }
            __syncthreads();
        }
    }
    grid_bar(sense);

    // ---- P9: gather per input row -------------------------------------------
    for (int i = gtid; i < n; i += GSTRIDE) {
        int j = g_inv[g_code[i]];
        ((float2*)out)[i] = ((const float2*)g_table2)[j];
    }
}

// ---------------------------------------------------------------------------

extern "C" void kernel_launch(void* const* d_in, const int* in_sizes, int n_in,
                              void* d_out, int out_size) {
    const float* z    = (const float*)d_in[0];
    const float* t    = (const float*)d_in[1];
    const float* W1   = (const float*)d_in[2];
    const float* b1   = (const float*)d_in[3];
    const float* W2   = (const float*)d_in[4];
    const float* b2   = (const float*)d_in[5];
    const float* W3   = (const float*)d_in[6];
    const float* b3   = (const float*)d_in[7];
    const float* W4   = (const float*)d_in[8];
    const float* b4   = (const float*)d_in[9];
    const float* W5   = (const float*)d_in[10];
    const float* b5   = (const float*)d_in[11];
    const float* W6   = (const float*)d_in[12];
    const float* b6   = (const float*)d_in[13];
    const float* Wout = (const float*)d_in[14];
    const float* bout = (const float*)d_in[15];
    int n = in_sizes[0];

    k_prep<<<264, 256>>>(z, t, W1, W2, W3, W4, W5, W6, Wout, n);
    k_mega<<<NBLK, NTHR>>>(z, t, b1, b2, b3, b4, b5, b6, bout, (float*)d_out, n);
}